// round 5
// baseline (speedup 1.0000x reference)
#include <cuda_runtime.h>
#include <cuda_bf16.h>
#include <cstdint>

#define BATCH 32
#define NA 8400
#define NJ 100
#define NC 80
#define KTOP 13
#define EPSV 1e-9f
#define CAND_CAP 1024
#define MAXMULTI 24576   // provable bound: <= 13*100*32/2 = 20800
#define NBX 32
#define NBY 32
#define NBINS (NBX * NBY)
#define INVBW (32.0f / 640.0f)   // 1 / 20px

// ---------------- device scratch ----------------
__device__ int           g_cnt[BATCH * NA];
__device__ int           g_minj[BATCH * NA];
__device__ float         g_alignsel[BATCH * NA];   // al at claimed anchor (races ok, see notes)
__device__ float         g_sel_iou[BATCH * NA];    // iou at claimed anchor
__device__ int           g_gt[BATCH * NA];
__device__ unsigned char g_pos[BATCH * NA];
__device__ unsigned int  g_posalign[BATCH * NJ];   // float bits, atomicMax (nonneg)
__device__ unsigned int  g_posovl[BATCH * NJ];
__device__ int           g_multi[MAXMULTI];
__device__ int           g_nmulti;
// spatial bins over anchor_points (batch-independent)
__device__ int           g_bincnt[NBINS];
__device__ int           g_binoff[NBINS + 1];
__device__ int           g_bincur[NBINS];
__device__ int           g_bin_a[NA];
__device__ float2        g_bin_xy[NA];

__device__ __forceinline__ float iou_box(float gx1, float gy1, float gx2, float gy2,
                                         float4 p, float garea) {
    float ix1 = fmaxf(gx1, p.x), iy1 = fmaxf(gy1, p.y);
    float ix2 = fminf(gx2, p.z), iy2 = fminf(gy2, p.w);
    float iw = fmaxf(ix2 - ix1, 0.0f), ih = fmaxf(iy2 - iy1, 0.0f);
    float inter = iw * ih;
    float parea = (p.z - p.x) * (p.w - p.y);
    return inter / (garea + parea - inter + EPSV);
}

__device__ __forceinline__ int binx(float x) {
    int v = (int)(x * INVBW);
    return max(0, min(NBX - 1, v));
}

// ---------------- K_init ----------------
__global__ void k_init() {
    int i = blockIdx.x * blockDim.x + threadIdx.x;
    if (i < BATCH * NA) { g_cnt[i] = 0; g_minj[i] = 0x7FFFFFFF; }
    if (i < BATCH * NJ) { g_posalign[i] = 0u; g_posovl[i] = 0u; }
    if (i < NBINS) g_bincnt[i] = 0;
    if (i == 0) g_nmulti = 0;
}

// ---------------- binning: count -> scan -> scatter ----------------
__global__ void k_bincount(const float* __restrict__ ap) {
    int a = blockIdx.x * blockDim.x + threadIdx.x;
    if (a >= NA) return;
    float2 apt = ((const float2*)ap)[a];
    atomicAdd(&g_bincnt[binx(apt.y) * NBX + binx(apt.x)], 1);
}

__global__ __launch_bounds__(NBINS) void k_binscan() {
    __shared__ int s[NBINS];
    int t = threadIdx.x;
    int v = g_bincnt[t];
    s[t] = v;
    __syncthreads();
    #pragma unroll
    for (int off = 1; off < NBINS; off <<= 1) {
        int x = (t >= off) ? s[t - off] : 0;
        __syncthreads();
        s[t] += x;
        __syncthreads();
    }
    int incl = s[t];
    g_binoff[t + 1] = incl;
    g_bincur[t] = incl - v;
    if (t == 0) g_binoff[0] = 0;
}

__global__ void k_binscatter(const float* __restrict__ ap) {
    int a = blockIdx.x * blockDim.x + threadIdx.x;
    if (a >= NA) return;
    float2 apt = ((const float2*)ap)[a];
    int bin = binx(apt.y) * NBX + binx(apt.x);
    int pos = atomicAdd(&g_bincur[bin], 1);
    g_bin_a[pos] = a;
    g_bin_xy[pos] = apt;
}

// ---------------- K1: per (b,j) binned candidates + exact top-13 ----------------
__global__ __launch_bounds__(128) void k_topk(
    const float* __restrict__ ps,    // pred_scores [b,a,c]
    const float* __restrict__ pb,    // pred_bboxes [b,a,4]
    const int*   __restrict__ glab,  // gt_labels [b,j]
    const float* __restrict__ gbb,   // gt_bboxes [b,j,4]
    const float* __restrict__ mgt)   // mask_gt [b,j]
{
    __shared__ unsigned long long s_cand[CAND_CAP];
    __shared__ float s_iou[CAND_CAP];
    __shared__ int s_n;

    int j = blockIdx.x, b = blockIdx.y;
    if (mgt[b * NJ + j] <= 0.0f) return;

    int tid = threadIdx.x;
    if (tid == 0) s_n = 0;

    const float4 gb4 = ((const float4*)gbb)[b * NJ + j];
    const float gx1 = gb4.x, gy1 = gb4.y, gx2 = gb4.z, gy2 = gb4.w;
    const float garea = (gx2 - gx1) * (gy2 - gy1);
    const int   lab = glab[b * NJ + j];
    __syncthreads();

    // bin range overlapping the GT box
    int bx0 = binx(gx1), bx1 = binx(gx2);
    int by0 = binx(gy1), by1 = binx(gy2);

    for (int by = by0; by <= by1; ++by) {
        int s = g_binoff[by * NBX + bx0];
        int e = g_binoff[by * NBX + bx1 + 1];
        for (int c = s + tid; c < e; c += 128) {
            float2 apt = g_bin_xy[c];
            float m = fminf(fminf(apt.x - gx1, apt.y - gy1),
                            fminf(gx2 - apt.x, gy2 - apt.y));
            if (m > EPSV) {
                int a = g_bin_a[c];
                float4 p = ((const float4*)pb)[(size_t)b * NA + a];
                float iou = iou_box(gx1, gy1, gx2, gy2, p, garea);
                float sc = ps[((size_t)b * NA + a) * NC + lab];
                float i2 = iou * iou;
                float al = sc * (i2 * i2 * i2);   // score * iou^6
                int slot = atomicAdd(&s_n, 1);
                if (slot < CAND_CAP) {
                    s_cand[slot] = ((unsigned long long)__float_as_uint(al) << 32)
                                 | (unsigned)(~a);
                    s_iou[slot] = iou;
                }
            }
        }
    }
    __syncthreads();

    // Warp 0: 13 iterative-max rounds (value desc, index asc via ~a)
    if (tid < 32) {
        int n = min(s_n, CAND_CAP);
        const int gbase = b * NA;
        for (int it = 0; it < KTOP && it < n; ++it) {
            unsigned long long bv = 0ULL; int bs = -1;
            for (int c = tid; c < n; c += 32) {
                unsigned long long v = s_cand[c];
                if (v > bv) { bv = v; bs = c; }
            }
            #pragma unroll
            for (int off = 16; off; off >>= 1) {
                unsigned long long ov = __shfl_xor_sync(0xFFFFFFFFu, bv, off);
                int os = __shfl_xor_sync(0xFFFFFFFFu, bs, off);
                if (ov > bv) { bv = ov; bs = os; }
            }
            if ((unsigned)(bv >> 32) == 0u) break;   // only zeros left
            if (tid == 0) {
                int a = (int)(~(unsigned)bv);
                atomicAdd(&g_cnt[gbase + a], 1);
                atomicMin(&g_minj[gbase + a], j);
                // stash al/iou: single-claim anchors get exact values
                // (multi-claim races are overwritten by k_resolve2 before use)
                g_alignsel[gbase + a] = __uint_as_float((unsigned)(bv >> 32));
                g_sel_iou[gbase + a]  = s_iou[bs];
                s_cand[bs] = 0ULL;
            }
            __syncwarp();
        }
    }
}

// ---------------- K2a: uniform resolution; compact multi-claim anchors ----------------
__global__ void k_resolve1() {
    int i = blockIdx.x * blockDim.x + threadIdx.x;
    if (i >= BATCH * NA) return;
    int s = g_cnt[i];
    if (s == 0) { g_gt[i] = 0; g_pos[i] = 0; return; }
    g_pos[i] = 1;
    if (s == 1) {
        int b = i / NA;
        int g = g_minj[i];
        g_gt[i] = g;
        atomicMax(&g_posalign[b * NJ + g], __float_as_uint(g_alignsel[i]));
        atomicMax(&g_posovl[b * NJ + g], __float_as_uint(g_sel_iou[i]));
    } else {
        int slot = atomicAdd(&g_nmulti, 1);
        if (slot < MAXMULTI) g_multi[slot] = i;
    }
}

// ---------------- K2b: grid-stride warp-per-multi-anchor argmax over 100 GTs ----------------
__global__ __launch_bounds__(256) void k_resolve2(
    const float* __restrict__ ps,
    const float* __restrict__ pb,
    const int*   __restrict__ glab,
    const float* __restrict__ gbb)
{
    int lane = threadIdx.x & 31;
    int warp0 = (blockIdx.x * blockDim.x + threadIdx.x) >> 5;
    int nwarps = (gridDim.x * blockDim.x) >> 5;
    int nm = min(g_nmulti, MAXMULTI);

    for (int gw = warp0; gw < nm; gw += nwarps) {
        int i = g_multi[gw];
        int b = i / NA;
        float4 p = ((const float4*)pb)[i];

        unsigned long long bv = 0ULL;
        for (int j = lane; j < NJ; j += 32) {
            float4 gb4 = ((const float4*)gbb)[b * NJ + j];
            float v = iou_box(gb4.x, gb4.y, gb4.z, gb4.w, p,
                              (gb4.z - gb4.x) * (gb4.w - gb4.y));
            unsigned long long key = ((unsigned long long)__float_as_uint(v) << 32)
                                   | (unsigned)(~j);
            bv = max(bv, key);
        }
        #pragma unroll
        for (int off = 16; off; off >>= 1)
            bv = max(bv, __shfl_xor_sync(0xFFFFFFFFu, bv, off));

        if (lane == 0) {
            int g = (int)(~(unsigned)bv);
            float iou = __uint_as_float((unsigned)(bv >> 32));
            int lab = glab[b * NJ + g];
            float sc = ps[(size_t)i * NC + lab];
            float i2 = iou * iou;
            float al = sc * (i2 * i2 * i2);
            g_gt[i] = g;
            g_alignsel[i] = al;
            atomicMax(&g_posalign[b * NJ + g], __float_as_uint(al));
            atomicMax(&g_posovl[b * NJ + g], __float_as_uint(iou));
        }
    }
}

// ---------------- K3: fused finalization (labels, bboxes, pos, one-hot scores) ----------------
__global__ __launch_bounds__(256) void k_final(
    const int*   __restrict__ glab,
    const float* __restrict__ gbb,
    float* __restrict__ out)
{
    int i = blockIdx.x * blockDim.x + threadIdx.x;
    if (i >= BATCH * NA) return;
    int b = i / NA;
    bool pos = g_pos[i] != 0;
    int g = g_gt[i];
    float norm = 0.0f; int lab = NC;
    if (pos) {
        int r = b * NJ + g;
        float pa = __uint_as_float(g_posalign[r]);
        float po = __uint_as_float(g_posovl[r]);
        norm = g_alignsel[i] * po / (pa + EPSV);
        lab = glab[r];
    }
    // layout: [labels | bboxes | scores | pos], all f32
    out[i] = (float)lab;
    ((float4*)(out + BATCH * NA))[i] = ((const float4*)gbb)[b * NJ + g];
    out[(size_t)BATCH * NA * 85 + i] = pos ? 1.0f : 0.0f;

    float4* sc = (float4*)(out + (size_t)BATCH * NA * 5 + (size_t)i * NC);
    int lq = lab >> 2, lr = lab & 3;
    #pragma unroll
    for (int q = 0; q < NC / 4; ++q) {
        float4 v = make_float4(0.f, 0.f, 0.f, 0.f);
        if (q == lq) ((float*)&v)[lr] = norm;   // lab==NC -> lq==20, never matches
        sc[q] = v;
    }
}

// ---------------- launch ----------------
extern "C" void kernel_launch(void* const* d_in, const int* in_sizes, int n_in,
                              void* d_out, int out_size) {
    const float* pred_scores  = (const float*)d_in[0];
    const float* pred_bboxes  = (const float*)d_in[1];
    const float* anchor_pts   = (const float*)d_in[2];
    const int*   gt_labels    = (const int*)d_in[3];
    const float* gt_bboxes    = (const float*)d_in[4];
    const float* mask_gt      = (const float*)d_in[5];
    float* out = (float*)d_out;

    k_init<<<(BATCH * NA + 255) / 256, 256>>>();
    k_bincount<<<(NA + 255) / 256, 256>>>(anchor_pts);
    k_binscan<<<1, NBINS>>>();
    k_binscatter<<<(NA + 255) / 256, 256>>>(anchor_pts);

    k_topk<<<dim3(NJ, BATCH), 128>>>(pred_scores, pred_bboxes,
                                     gt_labels, gt_bboxes, mask_gt);

    k_resolve1<<<(BATCH * NA + 255) / 256, 256>>>();

    k_resolve2<<<64, 256>>>(pred_scores, pred_bboxes, gt_labels, gt_bboxes);

    k_final<<<(BATCH * NA + 255) / 256, 256>>>(gt_labels, gt_bboxes, out);
}